// round 2
// baseline (speedup 1.0000x reference)
#include <cuda_runtime.h>
#include <cstddef>

#define TT 1024
#define BB 32
#define HH 512
#define GG 2048
#define NBLK 128
#define OUT1_ELEMS (TT*BB*HH)         // 16777216
#define BH (BB*HH)                    // 16384

// ---------------- device globals (scratch; no allocation allowed) -------------
__device__ float g_gi0[(size_t)TT * BB * GG];   // 256 MB: precomputed x @ w_ih0^T + b_ih0
__device__ float g_h0buf[2 * BH];               // double-buffered layer0 hidden
__device__ float g_h1buf[2 * BH];               // double-buffered layer1 hidden
__device__ unsigned g_bar;                      // barrier arrival counter
__device__ unsigned g_gen;                      // barrier generation

// swizzle: k -> (k&31)*16 + (k>>5); row stride 513 => conflict-free tiled reads
#define SW(k) ((((k) & 31) << 4) | ((k) >> 5))

// ======================= input-projection GEMM ===============================
// C[M=32768][N=2048] = A[M][512] * W[N][512]^T + bias;  C written to g_gi0
__global__ void __launch_bounds__(256) gemm_in2h(
    const float* __restrict__ A, const float* __restrict__ W,
    const float* __restrict__ bias)
{
    __shared__ float As[8][132];
    __shared__ float Bs[8][132];
    const int tid = threadIdx.x;
    const int n0 = blockIdx.x * 128;
    const int m0 = blockIdx.y * 128;
    const int tx = tid & 15, ty = tid >> 4;
    const int lrow = tid >> 1, lk4 = (tid & 1) * 4;
    const float* Ab = A + (size_t)(m0 + lrow) * 512 + lk4;
    const float* Wb = W + (size_t)(n0 + lrow) * 512 + lk4;

    float acc[8][8];
#pragma unroll
    for (int i = 0; i < 8; i++)
#pragma unroll
        for (int j = 0; j < 8; j++) acc[i][j] = 0.f;

    for (int k0 = 0; k0 < 512; k0 += 8) {
        float4 av = *(const float4*)(Ab + k0);
        float4 wv = *(const float4*)(Wb + k0);
        As[lk4 + 0][lrow] = av.x; As[lk4 + 1][lrow] = av.y;
        As[lk4 + 2][lrow] = av.z; As[lk4 + 3][lrow] = av.w;
        Bs[lk4 + 0][lrow] = wv.x; Bs[lk4 + 1][lrow] = wv.y;
        Bs[lk4 + 2][lrow] = wv.z; Bs[lk4 + 3][lrow] = wv.w;
        __syncthreads();
#pragma unroll
        for (int k = 0; k < 8; k++) {
            float a[8], b[8];
            *(float4*)&a[0] = *(const float4*)&As[k][ty * 8];
            *(float4*)&a[4] = *(const float4*)&As[k][ty * 8 + 4];
            *(float4*)&b[0] = *(const float4*)&Bs[k][tx * 8];
            *(float4*)&b[4] = *(const float4*)&Bs[k][tx * 8 + 4];
#pragma unroll
            for (int i = 0; i < 8; i++)
#pragma unroll
                for (int j = 0; j < 8; j++) acc[i][j] += a[i] * b[j];
        }
        __syncthreads();
    }

    float bv[8];
#pragma unroll
    for (int j = 0; j < 8; j++) bv[j] = bias[n0 + tx * 8 + j];
#pragma unroll
    for (int i = 0; i < 8; i++) {
        size_t row = (size_t)(m0 + ty * 8 + i);
        float* Crow = g_gi0 + row * 2048 + n0 + tx * 8;
#pragma unroll
        for (int j = 0; j < 8; j++) Crow[j] = acc[i][j] + bv[j];
    }
}

// ======================= persistent recurrence kernel ========================
__device__ __forceinline__ float sigf(float x) { return 1.f / (1.f + __expf(-x)); }

__device__ __forceinline__ void gridbar() {
    __syncthreads();
    if (threadIdx.x == 0) {
        __threadfence();
        unsigned g = *(volatile unsigned*)&g_gen;
        if (atomicAdd(&g_bar, 1u) == NBLK - 1) {
            g_bar = 0;
            __threadfence();
            *(volatile unsigned*)&g_gen = g + 1;
        } else {
            while (*(volatile unsigned*)&g_gen == g) { }
        }
    }
    __syncthreads();
}

__device__ __forceinline__ void stage_h(float* __restrict__ hs,
                                        const float* __restrict__ src, int tid) {
    // src: [32][512] contiguous -> hs: [32][513] swizzled
#pragma unroll 4
    for (int u4 = tid; u4 < 4096; u4 += 256) {
        int u = u4 << 2;
        int b = u >> 9, k = u & 511;
        float4 v = ((const float4*)src)[u4];
        float* hb = hs + b * 513;
        hb[SW(k)]     = v.x;
        hb[SW(k + 1)] = v.y;
        hb[SW(k + 2)] = v.z;
        hb[SW(k + 3)] = v.w;
    }
}

__device__ __forceinline__ void gemm_acc(const float* __restrict__ hs,
                                         const float* __restrict__ ws,
                                         int b0, int r0, int kc, float acc[8][4]) {
    const float* wp = ws + r0 * 513 + kc;
    const float* hp = hs + b0 * 513 + kc;
#pragma unroll 8
    for (int kk = 0; kk < 32; kk++) {
        int off = kk << 4;
        float w0 = wp[off], w1 = wp[off + 513], w2 = wp[off + 1026], w3 = wp[off + 1539];
#pragma unroll
        for (int i = 0; i < 8; i++) {
            float hv = hp[i * 513 + off];
            acc[i][0] += hv * w0;
            acc[i][1] += hv * w1;
            acc[i][2] += hv * w2;
            acc[i][3] += hv * w3;
        }
    }
}

__device__ __forceinline__ void reduce_combine(float acc[8][4], float* __restrict__ gsm,
                                               int kh, int kcl, int b0, int r0) {
#pragma unroll
    for (int i = 0; i < 8; i++)
#pragma unroll
        for (int j = 0; j < 4; j++) {
            float v = acc[i][j];
            v += __shfl_xor_sync(0xffffffffu, v, 1);
            v += __shfl_xor_sync(0xffffffffu, v, 2);
            v += __shfl_xor_sync(0xffffffffu, v, 4);
            acc[i][j] = v;
        }
    if (kh == 0) {
#pragma unroll
        for (int i = 0; i < 8; i++)
            if (i == kcl) {
#pragma unroll
                for (int j = 0; j < 4; j++) gsm[(r0 + j) * 32 + b0 + i] = acc[i][j];
            }
    }
    __syncthreads();
    if (kh == 1) {
#pragma unroll
        for (int i = 0; i < 8; i++)
            if (i == kcl) {
#pragma unroll
                for (int j = 0; j < 4; j++) gsm[(r0 + j) * 32 + b0 + i] += acc[i][j];
            }
    }
    __syncthreads();
}

__global__ void __launch_bounds__(256, 1) lstm_rec(
    const float* __restrict__ w_hh0, const float* __restrict__ b_hh0,
    const float* __restrict__ w_ih1, const float* __restrict__ w_hh1,
    const float* __restrict__ b_ih1, const float* __restrict__ b_hh1,
    const float* __restrict__ h0_in, const float* __restrict__ c0_in,
    float* __restrict__ dout)
{
    extern __shared__ float sm[];
    float* ws0  = sm;                 // 16*513 = 8208
    float* wsi1 = sm + 8208;
    float* wsh1 = sm + 16416;
    float* hs   = sm + 24624;         // 32*513 = 16416
    float* gsm  = sm + 41040;         // 16*32  = 512
    float* csm  = sm + 41552;         // 2*4*32 = 256

    const int tid = threadIdx.x;
    const int bid = blockIdx.x;
    const int J0 = bid << 2;

    // Stage this block's 16 weight rows per matrix (swizzled), once.
    for (int u = tid; u < 16 * 512; u += 256) {
        int r = u >> 9, k = u & 511;
        int gr = ((r >> 2) << 9) + J0 + (r & 3);  // global gate row g*512 + J0 + jl
        int d = r * 513 + SW(k);
        ws0[d]  = w_hh0[gr * 512 + k];
        wsi1[d] = w_ih1[gr * 512 + k];
        wsh1[d] = w_hh1[gr * 512 + k];
    }
    // Initialize hidden buffers at parity 1 (read by step 0).
    {
        int u = (bid << 8) + tid;   // 0..32767 covers h0_in (2,32,512)
        if (u < BH) g_h0buf[BH + u] = h0_in[u];
        else        g_h1buf[u]      = h0_in[u];   // BH + (u - BH) == u
    }
    // Cell state in smem, block-local: csm[layer*128 + jl*32 + b]
    {
        int l = tid >> 7, jl = (tid >> 5) & 3, b = tid & 31;
        csm[tid] = c0_in[(l << 14) + (b << 9) + J0 + jl];
    }

    const int lane = tid & 31, warp = tid >> 5;
    const int rg = warp >> 1, kh = warp & 1;
    const int bg = lane >> 3, kcl = lane & 7;
    const int kc = (kh << 3) + kcl;
    const int b0 = bg << 3, r0 = rg << 2;

    // loop-invariant biases for the elementwise threads
    float bI0 = 0, bF0 = 0, bG0 = 0, bO0 = 0;
    float bI1 = 0, bF1 = 0, bG1 = 0, bO1 = 0;
    if (tid < 128) {
        int jl = tid >> 5, Jj = J0 + jl;
        bI0 = b_hh0[Jj];        bF0 = b_hh0[512 + Jj];
        bG0 = b_hh0[1024 + Jj]; bO0 = b_hh0[1536 + Jj];
        bI1 = b_ih1[Jj] + b_hh1[Jj];
        bF1 = b_ih1[512 + Jj] + b_hh1[512 + Jj];
        bG1 = b_ih1[1024 + Jj] + b_hh1[1024 + Jj];
        bO1 = b_ih1[1536 + Jj] + b_hh1[1536 + Jj];
    }

    gridbar();

    float accv[8][4];

    for (int t = 0; t < TT; t++) {
        const int p = t & 1, q = p ^ 1;

        // prefetch gi0[t] for elementwise (hides L2/HBM latency behind the GEMM)
        float giI = 0, giF = 0, giG = 0, giO = 0;
        if (tid < 128) {
            int jl = tid >> 5, b = tid & 31, Jj = J0 + jl;
            const float* gi = g_gi0 + ((size_t)t << 16) + ((size_t)b << 11);
            giI = gi[Jj]; giF = gi[512 + Jj]; giG = gi[1024 + Jj]; giO = gi[1536 + Jj];
        }

        // ---------------- phase 0: layer 0 ----------------
        stage_h(hs, g_h0buf + (q << 14), tid);
        __syncthreads();
#pragma unroll
        for (int i = 0; i < 8; i++)
#pragma unroll
            for (int j = 0; j < 4; j++) accv[i][j] = 0.f;
        gemm_acc(hs, ws0, b0, r0, kc, accv);
        reduce_combine(accv, gsm, kh, kcl, b0, r0);

        if (tid < 128) {
            int jl = tid >> 5, b = tid & 31, Jj = J0 + jl;
            float gI = giI + gsm[jl * 32 + b] + bI0;
            float gF = giF + gsm[(4 + jl) * 32 + b] + bF0;
            float gG = giG + gsm[(8 + jl) * 32 + b] + bG0;
            float gO = giO + gsm[(12 + jl) * 32 + b] + bO0;
            float iv = sigf(gI), fv = sigf(gF), gv = tanhf(gG), ov = sigf(gO);
            float c = fv * csm[jl * 32 + b] + iv * gv;
            csm[jl * 32 + b] = c;
            float h = ov * tanhf(c);
            g_h0buf[(p << 14) + (b << 9) + Jj] = h;
            if (t == TT - 1) {
                dout[OUT1_ELEMS + (b << 9) + Jj] = h;                 // h_n[0]
                dout[OUT1_ELEMS + 2 * BH + (b << 9) + Jj] = c;        // c_n[0]
            }
        }

        gridbar();

        // ---------------- phase 1: layer 1 ----------------
        stage_h(hs, g_h0buf + (p << 14), tid);   // x1 = layer0 output at t
        __syncthreads();
#pragma unroll
        for (int i = 0; i < 8; i++)
#pragma unroll
            for (int j = 0; j < 4; j++) accv[i][j] = 0.f;
        gemm_acc(hs, wsi1, b0, r0, kc, accv);
        __syncthreads();
        stage_h(hs, g_h1buf + (q << 14), tid);   // h1_prev
        __syncthreads();
        gemm_acc(hs, wsh1, b0, r0, kc, accv);
        reduce_combine(accv, gsm, kh, kcl, b0, r0);

        if (tid < 128) {
            int jl = tid >> 5, b = tid & 31, Jj = J0 + jl;
            float gI = gsm[jl * 32 + b] + bI1;
            float gF = gsm[(4 + jl) * 32 + b] + bF1;
            float gG = gsm[(8 + jl) * 32 + b] + bG1;
            float gO = gsm[(12 + jl) * 32 + b] + bO1;
            float iv = sigf(gI), fv = sigf(gF), gv = tanhf(gG), ov = sigf(gO);
            float c = fv * csm[128 + jl * 32 + b] + iv * gv;
            csm[128 + jl * 32 + b] = c;
            float h = ov * tanhf(c);
            g_h1buf[(p << 14) + (b << 9) + Jj] = h;
            dout[((size_t)t << 14) + (b << 9) + Jj] = h;              // out1[t]
            if (t == TT - 1) {
                dout[OUT1_ELEMS + BH + (b << 9) + Jj] = h;            // h_n[1]
                dout[OUT1_ELEMS + 2 * BH + BH + (b << 9) + Jj] = c;   // c_n[1]
            }
        }
        // no grid barrier needed here: phase0(t+1) touches no buffer phase1(t)
        // writes, and phase1(t+1) is separated by the next gridbar.
    }
}

// ============================== launcher =====================================
extern "C" void kernel_launch(void* const* d_in, const int* in_sizes, int n_in,
                              void* d_out, int out_size) {
    const float* x     = (const float*)d_in[0];
    const float* w_ih0 = (const float*)d_in[1];
    const float* w_hh0 = (const float*)d_in[2];
    const float* b_ih0 = (const float*)d_in[3];
    const float* b_hh0 = (const float*)d_in[4];
    const float* w_ih1 = (const float*)d_in[5];
    const float* w_hh1 = (const float*)d_in[6];
    const float* b_ih1 = (const float*)d_in[7];
    const float* b_hh1 = (const float*)d_in[8];
    const float* h0    = (const float*)d_in[9];
    const float* c0    = (const float*)d_in[10];
    float* out = (float*)d_out;

    const int smem_bytes = 41808 * 4;  // 167232 B
    cudaFuncSetAttribute(lstm_rec, cudaFuncAttributeMaxDynamicSharedMemorySize,
                         smem_bytes);

    // 1) gi0 = x @ w_ih0^T + b_ih0  (fully parallel)
    gemm_in2h<<<dim3(16, 256), 256>>>(x, w_ih0, b_ih0);

    // 2) persistent fused 2-layer recurrence
    lstm_rec<<<NBLK, 256, smem_bytes>>>(w_hh0, b_hh0, w_ih1, w_hh1, b_ih1, b_hh1,
                                        h0, c0, out);
}

// round 3
// speedup vs baseline: 1.1710x; 1.1710x over previous
#include <cuda_runtime.h>
#include <cstddef>

#define TT 1024
#define BB 32
#define GG 2048
#define NBLK 128
#define OUT1_ELEMS (TT*BB*512)
#define BH (BB*512)

// smem row stride (floats) for weight rows and h rows; multiple of 4 for LDS.128
#define WS 640
// k -> smem offset: (k, k+32, k+64, k+96) are adjacent words => float2/float4 packs
#define OFFK(k) ((((k) & 31) * 20) + ((k) >> 5))

// ---------------- device globals (scratch; no allocation allowed) ------------
__device__ float g_gi0[(size_t)TT * BB * GG];   // precomputed x @ w_ih0^T + b_ih0
__device__ float g_h0buf[2 * BH];
__device__ float g_h1buf[2 * BH];
__device__ unsigned g_bar;
__device__ unsigned g_gen;

// ======================= input-projection GEMM ===============================
__global__ void __launch_bounds__(256) gemm_in2h(
    const float* __restrict__ A, const float* __restrict__ W,
    const float* __restrict__ bias)
{
    __shared__ float As[8][132];
    __shared__ float Bs[8][132];
    const int tid = threadIdx.x;
    const int n0 = blockIdx.x * 128;
    const int m0 = blockIdx.y * 128;
    const int tx = tid & 15, ty = tid >> 4;
    const int lrow = tid >> 1, lk4 = (tid & 1) * 4;
    const float* Ab = A + (size_t)(m0 + lrow) * 512 + lk4;
    const float* Wb = W + (size_t)(n0 + lrow) * 512 + lk4;

    float acc[8][8];
#pragma unroll
    for (int i = 0; i < 8; i++)
#pragma unroll
        for (int j = 0; j < 8; j++) acc[i][j] = 0.f;

    for (int k0 = 0; k0 < 512; k0 += 8) {
        float4 av = *(const float4*)(Ab + k0);
        float4 wv = *(const float4*)(Wb + k0);
        As[lk4 + 0][lrow] = av.x; As[lk4 + 1][lrow] = av.y;
        As[lk4 + 2][lrow] = av.z; As[lk4 + 3][lrow] = av.w;
        Bs[lk4 + 0][lrow] = wv.x; Bs[lk4 + 1][lrow] = wv.y;
        Bs[lk4 + 2][lrow] = wv.z; Bs[lk4 + 3][lrow] = wv.w;
        __syncthreads();
#pragma unroll
        for (int k = 0; k < 8; k++) {
            float a[8], b[8];
            *(float4*)&a[0] = *(const float4*)&As[k][ty * 8];
            *(float4*)&a[4] = *(const float4*)&As[k][ty * 8 + 4];
            *(float4*)&b[0] = *(const float4*)&Bs[k][tx * 8];
            *(float4*)&b[4] = *(const float4*)&Bs[k][tx * 8 + 4];
#pragma unroll
            for (int i = 0; i < 8; i++)
#pragma unroll
                for (int j = 0; j < 8; j++) acc[i][j] += a[i] * b[j];
        }
        __syncthreads();
    }

    float bv[8];
#pragma unroll
    for (int j = 0; j < 8; j++) bv[j] = bias[n0 + tx * 8 + j];
#pragma unroll
    for (int i = 0; i < 8; i++) {
        size_t row = (size_t)(m0 + ty * 8 + i);
        float* Crow = g_gi0 + row * 2048 + n0 + tx * 8;
#pragma unroll
        for (int j = 0; j < 8; j++) Crow[j] = acc[i][j] + bv[j];
    }
}

// ======================= persistent recurrence kernel ========================
__device__ __forceinline__ float sigf(float x) { return 1.f / (1.f + __expf(-x)); }

// packed dual fp32 FMA (Blackwell FFMA2) — identical numerics to 2x fmaf
__device__ __forceinline__ unsigned long long fma2(unsigned long long a,
                                                   unsigned long long b,
                                                   unsigned long long c) {
    unsigned long long d;
    asm("fma.rn.f32x2 %0, %1, %2, %3;" : "=l"(d) : "l"(a), "l"(b), "l"(c));
    return d;
}

__device__ __forceinline__ void gridbar() {
    __syncthreads();
    if (threadIdx.x == 0) {
        __threadfence();
        unsigned g = *(volatile unsigned*)&g_gen;
        if (atomicAdd(&g_bar, 1u) == NBLK - 1) {
            g_bar = 0;
            __threadfence();
            *(volatile unsigned*)&g_gen = g + 1;
        } else {
            while (*(volatile unsigned*)&g_gen == g) { }
        }
    }
    __syncthreads();
}

__device__ __forceinline__ void stage_h(float* __restrict__ hs,
                                        const float* __restrict__ src, int tid) {
    // src: [32][512] contiguous -> hs: [32][WS] in OFFK layout
#pragma unroll 2
    for (int u4 = tid; u4 < 4096; u4 += 512) {
        int u = u4 << 2;
        int b = u >> 9, k = u & 511;
        float4 v = ((const float4*)src)[u4];
        float* hb = hs + b * WS;
        hb[OFFK(k)]     = v.x;
        hb[OFFK(k + 1)] = v.y;
        hb[OFFK(k + 2)] = v.z;
        hb[OFFK(k + 3)] = v.w;
    }
}

// 8 batch x 4 rows register tile; thread covers 16 ks (kc + 32*m, m=0..15)
// as 4 x LDS.128 per operand row, each feeding 2 x FFMA2.
__device__ __forceinline__ void gemm_acc(const float* __restrict__ hs,
                                         const float* __restrict__ ws,
                                         int b0, int r0, int kc,
                                         unsigned long long acc[8][4]) {
    const float* wp = ws + r0 * WS + kc * 20;
    const float* hp = hs + b0 * WS + kc * 20;
#pragma unroll
    for (int u = 0; u < 4; u++) {
        unsigned long long wv0[4], wv1[4];
#pragma unroll
        for (int j = 0; j < 4; j++) {
            ulonglong2 t = *reinterpret_cast<const ulonglong2*>(wp + j * WS + u * 4);
            wv0[j] = t.x; wv1[j] = t.y;
        }
#pragma unroll
        for (int i = 0; i < 8; i++) {
            ulonglong2 hv = *reinterpret_cast<const ulonglong2*>(hp + i * WS + u * 4);
#pragma unroll
            for (int j = 0; j < 4; j++) {
                acc[i][j] = fma2(hv.x, wv0[j], acc[i][j]);
                acc[i][j] = fma2(hv.y, wv1[j], acc[i][j]);
            }
        }
    }
}

// reduce packed acc over lanes' kcl (8-way shfl), write per-kh partial to psm
__device__ __forceinline__ void red_write(unsigned long long acc[8][4],
                                          float* __restrict__ psm,
                                          int kh, int kcl, int b0, int r0) {
#pragma unroll
    for (int i = 0; i < 8; i++) {
#pragma unroll
        for (int j = 0; j < 4; j++) {
            float2 f = *reinterpret_cast<float2*>(&acc[i][j]);
            float v = f.x + f.y;
            v += __shfl_xor_sync(0xffffffffu, v, 1);
            v += __shfl_xor_sync(0xffffffffu, v, 2);
            v += __shfl_xor_sync(0xffffffffu, v, 4);
            acc[i][j] = (unsigned long long)__float_as_uint(v);  // stash lo
        }
        if (i == kcl) {
#pragma unroll
            for (int j = 0; j < 4; j++) {
                float v = __uint_as_float((unsigned)acc[i][j]);
                psm[kh * 512 + (r0 + j) * 32 + b0 + i] = v;
            }
        }
    }
}

__global__ void __launch_bounds__(512, 1) lstm_rec(
    const float* __restrict__ w_hh0, const float* __restrict__ b_hh0,
    const float* __restrict__ w_ih1, const float* __restrict__ w_hh1,
    const float* __restrict__ b_ih1, const float* __restrict__ b_hh1,
    const float* __restrict__ h0_in, const float* __restrict__ c0_in,
    float* __restrict__ dout)
{
    extern __shared__ float sm[];
    float* ws0  = sm;                 // 16*WS = 10240
    float* wsi1 = sm + 10240;
    float* wsh1 = sm + 20480;
    float* hs   = sm + 30720;         // 32*WS = 20480
    float* psm  = sm + 51200;         // 4*16*32 = 2048
    float* csm  = sm + 53248;         // 256

    const int tid = threadIdx.x;
    const int bid = blockIdx.x;
    const int J0 = bid << 2;

    // Stage this block's 16 weight rows per matrix (OFFK layout), once.
    for (int u = tid; u < 16 * 512; u += 512) {
        int r = u >> 9, k = u & 511;
        int gr = ((r >> 2) << 9) + J0 + (r & 3);  // gate g*512 + J0 + jl
        int d = r * WS + OFFK(k);
        ws0[d]  = w_hh0[gr * 512 + k];
        wsi1[d] = w_ih1[gr * 512 + k];
        wsh1[d] = w_hh1[gr * 512 + k];
    }
    // Initialize hidden buffers at parity 1 (read by step 0).
    {
        int g = (bid << 9) + tid;       // 0..65535; h0_in has 2*BH elems
        if (g < BH)          g_h0buf[BH + g] = h0_in[g];
        else if (g < 2 * BH) g_h1buf[g]      = h0_in[g];
    }
    // Cell state in smem: csm[layer*128 + jl*32 + b]
    if (tid < 256) {
        int l = tid >> 7, jl = (tid >> 5) & 3, b = tid & 31;
        csm[tid] = c0_in[(l << 14) + (b << 9) + J0 + jl];
    }

    const int lane = tid & 31, warp = tid >> 5;
    const int rg = warp & 3, kh = warp >> 2;
    const int bg = lane >> 3, kcl = lane & 7;
    const int kc = (kh << 3) + kcl;          // 0..31
    const int b0 = bg << 3, r0 = rg << 2;

    float bI0 = 0, bF0 = 0, bG0 = 0, bO0 = 0;
    float bI1 = 0, bF1 = 0, bG1 = 0, bO1 = 0;
    if (tid < 128) {
        int jl = tid >> 5, Jj = J0 + jl;
        bI0 = b_hh0[Jj];        bF0 = b_hh0[512 + Jj];
        bG0 = b_hh0[1024 + Jj]; bO0 = b_hh0[1536 + Jj];
        bI1 = b_ih1[Jj] + b_hh1[Jj];
        bF1 = b_ih1[512 + Jj] + b_hh1[512 + Jj];
        bG1 = b_ih1[1024 + Jj] + b_hh1[1024 + Jj];
        bO1 = b_ih1[1536 + Jj] + b_hh1[1536 + Jj];
    }

    gridbar();

    unsigned long long acc[8][4];

    for (int t = 0; t < TT; t++) {
        const int p = t & 1, q = p ^ 1;

        // prefetch gi0[t] for the elementwise threads
        float giI = 0, giF = 0, giG = 0, giO = 0;
        if (tid < 128) {
            int jl = tid >> 5, b = tid & 31, Jj = J0 + jl;
            const float* gi = g_gi0 + ((size_t)t << 16) + ((size_t)b << 11);
            giI = gi[Jj]; giF = gi[512 + Jj]; giG = gi[1024 + Jj]; giO = gi[1536 + Jj];
        }

        // ---------------- phase 0: layer 0 ----------------
        stage_h(hs, g_h0buf + (q << 14), tid);
        __syncthreads();
#pragma unroll
        for (int i = 0; i < 8; i++)
#pragma unroll
            for (int j = 0; j < 4; j++) acc[i][j] = 0ull;
        gemm_acc(hs, ws0, b0, r0, kc, acc);
        red_write(acc, psm, kh, kcl, b0, r0);
        __syncthreads();

        if (tid < 128) {
            int jl = tid >> 5, b = tid & 31, Jj = J0 + jl;
            float gI = giI + bI0, gF = giF + bF0, gG = giG + bG0, gO = giO + bO0;
#pragma unroll
            for (int z = 0; z < 4; z++) {
                const float* pz = psm + z * 512;
                gI += pz[jl * 32 + b];
                gF += pz[(4 + jl) * 32 + b];
                gG += pz[(8 + jl) * 32 + b];
                gO += pz[(12 + jl) * 32 + b];
            }
            float iv = sigf(gI), fv = sigf(gF), gv = tanhf(gG), ov = sigf(gO);
            float c = fv * csm[jl * 32 + b] + iv * gv;
            csm[jl * 32 + b] = c;
            float h = ov * tanhf(c);
            g_h0buf[(p << 14) + (b << 9) + Jj] = h;
            if (t == TT - 1) {
                dout[OUT1_ELEMS + (b << 9) + Jj] = h;
                dout[OUT1_ELEMS + 2 * BH + (b << 9) + Jj] = c;
            }
        }

        gridbar();

        // ---------------- phase 1: layer 1 ----------------
        stage_h(hs, g_h0buf + (p << 14), tid);   // x1 = layer0 output at t
        __syncthreads();
#pragma unroll
        for (int i = 0; i < 8; i++)
#pragma unroll
            for (int j = 0; j < 4; j++) acc[i][j] = 0ull;
        gemm_acc(hs, wsi1, b0, r0, kc, acc);
        __syncthreads();
        stage_h(hs, g_h1buf + (q << 14), tid);   // h1_prev
        __syncthreads();
        gemm_acc(hs, wsh1, b0, r0, kc, acc);
        red_write(acc, psm, kh, kcl, b0, r0);
        __syncthreads();

        if (tid < 128) {
            int jl = tid >> 5, b = tid & 31, Jj = J0 + jl;
            float gI = bI1, gF = bF1, gG = bG1, gO = bO1;
#pragma unroll
            for (int z = 0; z < 4; z++) {
                const float* pz = psm + z * 512;
                gI += pz[jl * 32 + b];
                gF += pz[(4 + jl) * 32 + b];
                gG += pz[(8 + jl) * 32 + b];
                gO += pz[(12 + jl) * 32 + b];
            }
            float iv = sigf(gI), fv = sigf(gF), gv = tanhf(gG), ov = sigf(gO);
            float c = fv * csm[128 + jl * 32 + b] + iv * gv;
            csm[128 + jl * 32 + b] = c;
            float h = ov * tanhf(c);
            g_h1buf[(p << 14) + (b << 9) + Jj] = h;
            dout[((size_t)t << 14) + (b << 9) + Jj] = h;
            if (t == TT - 1) {
                dout[OUT1_ELEMS + BH + (b << 9) + Jj] = h;
                dout[OUT1_ELEMS + 2 * BH + BH + (b << 9) + Jj] = c;
            }
        }
        // no grid barrier needed here (see round-1 analysis)
    }
}

// ============================== launcher =====================================
extern "C" void kernel_launch(void* const* d_in, const int* in_sizes, int n_in,
                              void* d_out, int out_size) {
    const float* x     = (const float*)d_in[0];
    const float* w_ih0 = (const float*)d_in[1];
    const float* w_hh0 = (const float*)d_in[2];
    const float* b_ih0 = (const float*)d_in[3];
    const float* b_hh0 = (const float*)d_in[4];
    const float* w_ih1 = (const float*)d_in[5];
    const float* w_hh1 = (const float*)d_in[6];
    const float* b_ih1 = (const float*)d_in[7];
    const float* b_hh1 = (const float*)d_in[8];
    const float* h0    = (const float*)d_in[9];
    const float* c0    = (const float*)d_in[10];
    float* out = (float*)d_out;

    const int smem_bytes = 53504 * 4;  // 214016 B
    cudaFuncSetAttribute(lstm_rec, cudaFuncAttributeMaxDynamicSharedMemorySize,
                         smem_bytes);

    gemm_in2h<<<dim3(16, 256), 256>>>(x, w_ih0, b_ih0);
    lstm_rec<<<NBLK, 512, smem_bytes>>>(w_hh0, b_hh0, w_ih1, w_hh1, b_ih1, b_hh1,
                                        h0, c0, out);
}

// round 4
// speedup vs baseline: 1.2358x; 1.0553x over previous
#include <cuda_runtime.h>
#include <cstddef>

#define TT 1024
#define BB 32
#define NBLK 128
#define OUT1_ELEMS (TT*BB*512)
#define BH (BB*512)

#define WTS 20      // weight smem stride per k (16 rows + 4 pad)
#define HSS 516     // h smem row stride (conflict-free for LDS.32 pattern)
#define PSS 132     // psm row stride: 32 batches * 4 kh + 4 pad

// ---------------- device globals (scratch; no allocation allowed) ------------
__device__ float g_gi0[(size_t)TT * BB * 2048];
__device__ float g_h0buf[2 * BH];
__device__ float g_h1buf[2 * BH];
__device__ unsigned g_bar;
__device__ unsigned g_gen;

// ======================= input-projection GEMM ===============================
__global__ void __launch_bounds__(256) gemm_in2h(
    const float* __restrict__ A, const float* __restrict__ W,
    const float* __restrict__ bias)
{
    __shared__ float As[8][132];
    __shared__ float Bs[8][132];
    const int tid = threadIdx.x;
    const int n0 = blockIdx.x * 128;
    const int m0 = blockIdx.y * 128;
    const int tx = tid & 15, ty = tid >> 4;
    const int lrow = tid >> 1, lk4 = (tid & 1) * 4;
    const float* Ab = A + (size_t)(m0 + lrow) * 512 + lk4;
    const float* Wb = W + (size_t)(n0 + lrow) * 512 + lk4;

    float acc[8][8];
#pragma unroll
    for (int i = 0; i < 8; i++)
#pragma unroll
        for (int j = 0; j < 8; j++) acc[i][j] = 0.f;

    for (int k0 = 0; k0 < 512; k0 += 8) {
        float4 av = *(const float4*)(Ab + k0);
        float4 wv = *(const float4*)(Wb + k0);
        As[lk4 + 0][lrow] = av.x; As[lk4 + 1][lrow] = av.y;
        As[lk4 + 2][lrow] = av.z; As[lk4 + 3][lrow] = av.w;
        Bs[lk4 + 0][lrow] = wv.x; Bs[lk4 + 1][lrow] = wv.y;
        Bs[lk4 + 2][lrow] = wv.z; Bs[lk4 + 3][lrow] = wv.w;
        __syncthreads();
#pragma unroll
        for (int k = 0; k < 8; k++) {
            float a[8], b[8];
            *(float4*)&a[0] = *(const float4*)&As[k][ty * 8];
            *(float4*)&a[4] = *(const float4*)&As[k][ty * 8 + 4];
            *(float4*)&b[0] = *(const float4*)&Bs[k][tx * 8];
            *(float4*)&b[4] = *(const float4*)&Bs[k][tx * 8 + 4];
#pragma unroll
            for (int i = 0; i < 8; i++)
#pragma unroll
                for (int j = 0; j < 8; j++) acc[i][j] += a[i] * b[j];
        }
        __syncthreads();
    }

    float bv[8];
#pragma unroll
    for (int j = 0; j < 8; j++) bv[j] = bias[n0 + tx * 8 + j];
#pragma unroll
    for (int i = 0; i < 8; i++) {
        size_t row = (size_t)(m0 + ty * 8 + i);
        float* Crow = g_gi0 + row * 2048 + n0 + tx * 8;
#pragma unroll
        for (int j = 0; j < 8; j++) Crow[j] = acc[i][j] + bv[j];
    }
}

// ======================= persistent recurrence kernel ========================
__device__ __forceinline__ float sigf(float x) {
    float e = __expf(fminf(-x, 80.f));
    return __fdividef(1.f, 1.f + e);
}
__device__ __forceinline__ float tanhfast(float x) {
    float e = __expf(fminf(2.f * x, 80.f));
    return 1.f - __fdividef(2.f, e + 1.f);
}

__device__ __forceinline__ unsigned long long fma2(unsigned long long a,
                                                   unsigned long long b,
                                                   unsigned long long c) {
    unsigned long long d;
    asm("fma.rn.f32x2 %0, %1, %2, %3;" : "=l"(d) : "l"(a), "l"(b), "l"(c));
    return d;
}
__device__ __forceinline__ unsigned long long addf2(unsigned long long a,
                                                    unsigned long long b) {
    unsigned long long d;
    asm("add.rn.f32x2 %0, %1, %2;" : "=l"(d) : "l"(a), "l"(b));
    return d;
}

__device__ __forceinline__ void gridbar() {
    __syncthreads();
    if (threadIdx.x == 0) {
        __threadfence();
        unsigned g = *(volatile unsigned*)&g_gen;
        if (atomicAdd(&g_bar, 1u) == NBLK - 1) {
            g_bar = 0;
            __threadfence();
            *(volatile unsigned*)&g_gen = g + 1;
        } else {
            while (*(volatile unsigned*)&g_gen == g) { }
        }
    }
    __syncthreads();
}

// plain copy: src [32][512] contiguous -> hs rows of stride HSS
__device__ __forceinline__ void stage_h(float* __restrict__ hs,
                                        const float* __restrict__ src, int tid) {
#pragma unroll
    for (int it = 0; it < 8; it++) {
        int u4 = tid + it * 512;
        int b = u4 >> 7, k4 = (u4 & 127) << 2;
        *(float4*)(hs + b * HSS + k4) = ((const float4*)src)[u4];
    }
}

// warp covers: 2 batches (per thread) x 16 rows (8 f32x2 row-pairs) x 128 k
__device__ __forceinline__ void gemm_rp(const float* __restrict__ hs,
                                        const float* __restrict__ wt,
                                        int hbase, int kbase,
                                        unsigned long long acc[2][8]) {
    const float* hp = hs + hbase + kbase;
    const float* wp = wt + kbase * WTS;
#pragma unroll 4
    for (int m = 0; m < 16; m++) {
        float h0 = hp[m * 8];
        float h1 = hp[HSS + m * 8];
        unsigned long long H0, H1;
        asm("mov.b64 %0, {%1, %1};" : "=l"(H0) : "f"(h0));
        asm("mov.b64 %0, {%1, %1};" : "=l"(H1) : "f"(h1));
        const float* w = wp + m * 8 * WTS;
        ulonglong2 w01 = *(const ulonglong2*)(w);
        ulonglong2 w23 = *(const ulonglong2*)(w + 4);
        ulonglong2 w45 = *(const ulonglong2*)(w + 8);
        ulonglong2 w67 = *(const ulonglong2*)(w + 12);
        acc[0][0] = fma2(H0, w01.x, acc[0][0]); acc[1][0] = fma2(H1, w01.x, acc[1][0]);
        acc[0][1] = fma2(H0, w01.y, acc[0][1]); acc[1][1] = fma2(H1, w01.y, acc[1][1]);
        acc[0][2] = fma2(H0, w23.x, acc[0][2]); acc[1][2] = fma2(H1, w23.x, acc[1][2]);
        acc[0][3] = fma2(H0, w23.y, acc[0][3]); acc[1][3] = fma2(H1, w23.y, acc[1][3]);
        acc[0][4] = fma2(H0, w45.x, acc[0][4]); acc[1][4] = fma2(H1, w45.x, acc[1][4]);
        acc[0][5] = fma2(H0, w45.y, acc[0][5]); acc[1][5] = fma2(H1, w45.y, acc[1][5]);
        acc[0][6] = fma2(H0, w67.x, acc[0][6]); acc[1][6] = fma2(H1, w67.x, acc[1][6]);
        acc[0][7] = fma2(H0, w67.y, acc[0][7]); acc[1][7] = fma2(H1, w67.y, acc[1][7]);
    }
}

// reduce over the 8 kcl lanes; lane kcl writes row-pair j2 == kcl to psm[r][b][kh]
__device__ __forceinline__ void red_write_rp(unsigned long long acc[2][8],
                                             float* __restrict__ psm,
                                             int kh, int kcl, int b0t) {
#pragma unroll
    for (int j2 = 0; j2 < 8; j2++) {
#pragma unroll
        for (int b2 = 0; b2 < 2; b2++) {
            unsigned long long v = acc[b2][j2];
            v = addf2(v, __shfl_xor_sync(0xffffffffu, v, 1));
            v = addf2(v, __shfl_xor_sync(0xffffffffu, v, 2));
            v = addf2(v, __shfl_xor_sync(0xffffffffu, v, 4));
            acc[b2][j2] = v;
        }
        if (j2 == kcl) {
            float2 f0 = *(float2*)&acc[0][j2];
            float2 f1 = *(float2*)&acc[1][j2];
            psm[(2 * j2) * PSS     + b0t * 4       + kh] = f0.x;
            psm[(2 * j2 + 1) * PSS + b0t * 4       + kh] = f0.y;
            psm[(2 * j2) * PSS     + (b0t + 1) * 4 + kh] = f1.x;
            psm[(2 * j2 + 1) * PSS + (b0t + 1) * 4 + kh] = f1.y;
        }
    }
}

__global__ void __launch_bounds__(512, 1) lstm_rec(
    const float* __restrict__ w_hh0, const float* __restrict__ b_hh0,
    const float* __restrict__ w_ih1, const float* __restrict__ w_hh1,
    const float* __restrict__ b_ih1, const float* __restrict__ b_hh1,
    const float* __restrict__ h0_in, const float* __restrict__ c0_in,
    float* __restrict__ dout)
{
    extern __shared__ float sm[];
    float* ws0t  = sm;                    // 512*20 = 10240
    float* wsi1t = sm + 10240;
    float* wsh1t = sm + 20480;
    float* hs    = sm + 30720;            // 32*516 = 16512
    float* psm   = sm + 47232;            // 16*132 = 2112
    float* csm   = sm + 49344;            // 256

    const int tid = threadIdx.x;
    const int bid = blockIdx.x;
    const int J0 = bid << 2;

    // Stage 16 weight rows per matrix, transposed to k-major [k][16].
    for (int u = tid; u < 16 * 512; u += 512) {
        int r = u >> 9, k = u & 511;
        int gr = ((r >> 2) << 9) + J0 + (r & 3);   // gate g*512 + J0 + jl
        int d = k * WTS + r;
        ws0t[d]  = w_hh0[gr * 512 + k];
        wsi1t[d] = w_ih1[gr * 512 + k];
        wsh1t[d] = w_hh1[gr * 512 + k];
    }
    // init hidden buffers at parity 1 (read by step 0)
    {
        int g = (bid << 9) + tid;
        if (g < BH)          g_h0buf[BH + g] = h0_in[g];
        else if (g < 2 * BH) g_h1buf[g]      = h0_in[g];
    }
    if (tid < 256) {
        int l = tid >> 7, jl = (tid >> 5) & 3, b = tid & 31;
        csm[tid] = c0_in[(l << 14) + (b << 9) + J0 + jl];
    }

    const int lane = tid & 31, warp = tid >> 5;
    const int bgrp = warp & 3, kh = warp >> 2;
    const int kcl = lane & 7, bsub = lane >> 3;
    const int b0t = bgrp * 8 + bsub * 2;
    const int kbase = kh * 128 + kcl;
    const int hbase = b0t * HSS;

    float bI0 = 0, bF0 = 0, bG0 = 0, bO0 = 0;
    float bI1 = 0, bF1 = 0, bG1 = 0, bO1 = 0;
    if (tid < 128) {
        int jl = tid >> 5, Jj = J0 + jl;
        bI0 = b_hh0[Jj];        bF0 = b_hh0[512 + Jj];
        bG0 = b_hh0[1024 + Jj]; bO0 = b_hh0[1536 + Jj];
        bI1 = b_ih1[Jj] + b_hh1[Jj];
        bF1 = b_ih1[512 + Jj] + b_hh1[512 + Jj];
        bG1 = b_ih1[1024 + Jj] + b_hh1[1024 + Jj];
        bO1 = b_ih1[1536 + Jj] + b_hh1[1536 + Jj];
    }

    gridbar();

    unsigned long long acc[2][8];

    for (int t = 0; t < TT; t++) {
        const int p = t & 1, q = p ^ 1;

        float giI = 0, giF = 0, giG = 0, giO = 0;
        if (tid < 128) {
            int jl = tid >> 5, b = tid & 31, Jj = J0 + jl;
            const float* gi = g_gi0 + ((size_t)t << 16) + ((size_t)b << 11);
            giI = gi[Jj]; giF = gi[512 + Jj]; giG = gi[1024 + Jj]; giO = gi[1536 + Jj];
        }

        // ---------------- phase 0: layer 0 ----------------
        stage_h(hs, g_h0buf + (q << 14), tid);
        __syncthreads();
#pragma unroll
        for (int b2 = 0; b2 < 2; b2++)
#pragma unroll
            for (int j2 = 0; j2 < 8; j2++) acc[b2][j2] = 0ull;
        gemm_rp(hs, ws0t, hbase, kbase, acc);
        red_write_rp(acc, psm, kh, kcl, b0t);
        __syncthreads();

        if (tid < 128) {
            int jl = tid >> 5, b = tid & 31, Jj = J0 + jl;
            float4 vI = *(const float4*)(psm + (jl) * PSS + b * 4);
            float4 vF = *(const float4*)(psm + (4 + jl) * PSS + b * 4);
            float4 vG = *(const float4*)(psm + (8 + jl) * PSS + b * 4);
            float4 vO = *(const float4*)(psm + (12 + jl) * PSS + b * 4);
            float gI = giI + bI0 + vI.x + vI.y + vI.z + vI.w;
            float gF = giF + bF0 + vF.x + vF.y + vF.z + vF.w;
            float gG = giG + bG0 + vG.x + vG.y + vG.z + vG.w;
            float gO = giO + bO0 + vO.x + vO.y + vO.z + vO.w;
            float iv = sigf(gI), fv = sigf(gF), gv = tanhfast(gG), ov = sigf(gO);
            float c = fv * csm[jl * 32 + b] + iv * gv;
            csm[jl * 32 + b] = c;
            float h = ov * tanhfast(c);
            g_h0buf[(p << 14) + (b << 9) + Jj] = h;
            if (t == TT - 1) {
                dout[OUT1_ELEMS + (b << 9) + Jj] = h;
                dout[OUT1_ELEMS + 2 * BH + (b << 9) + Jj] = c;
            }
        }

        gridbar();

        // ---------------- phase 1: layer 1 ----------------
        stage_h(hs, g_h0buf + (p << 14), tid);   // x1 = layer0 out at t
        __syncthreads();
#pragma unroll
        for (int b2 = 0; b2 < 2; b2++)
#pragma unroll
            for (int j2 = 0; j2 < 8; j2++) acc[b2][j2] = 0ull;
        gemm_rp(hs, wsi1t, hbase, kbase, acc);
        __syncthreads();
        stage_h(hs, g_h1buf + (q << 14), tid);   // h1_prev
        __syncthreads();
        gemm_rp(hs, wsh1t, hbase, kbase, acc);
        red_write_rp(acc, psm, kh, kcl, b0t);
        __syncthreads();

        if (tid < 128) {
            int jl = tid >> 5, b = tid & 31, Jj = J0 + jl;
            float4 vI = *(const float4*)(psm + (jl) * PSS + b * 4);
            float4 vF = *(const float4*)(psm + (4 + jl) * PSS + b * 4);
            float4 vG = *(const float4*)(psm + (8 + jl) * PSS + b * 4);
            float4 vO = *(const float4*)(psm + (12 + jl) * PSS + b * 4);
            float gI = bI1 + vI.x + vI.y + vI.z + vI.w;
            float gF = bF1 + vF.x + vF.y + vF.z + vF.w;
            float gG = bG1 + vG.x + vG.y + vG.z + vG.w;
            float gO = bO1 + vO.x + vO.y + vO.z + vO.w;
            float iv = sigf(gI), fv = sigf(gF), gv = tanhfast(gG), ov = sigf(gO);
            float c = fv * csm[128 + jl * 32 + b] + iv * gv;
            csm[128 + jl * 32 + b] = c;
            float h = ov * tanhfast(c);
            g_h1buf[(p << 14) + (b << 9) + Jj] = h;
            dout[((size_t)t << 14) + (b << 9) + Jj] = h;
            if (t == TT - 1) {
                dout[OUT1_ELEMS + BH + (b << 9) + Jj] = h;
                dout[OUT1_ELEMS + 2 * BH + BH + (b << 9) + Jj] = c;
            }
        }
        // no grid barrier needed here (phase0(t+1) deps protected by mid barrier)
    }
}

// ============================== launcher =====================================
extern "C" void kernel_launch(void* const* d_in, const int* in_sizes, int n_in,
                              void* d_out, int out_size) {
    const float* x     = (const float*)d_in[0];
    const float* w_ih0 = (const float*)d_in[1];
    const float* w_hh0 = (const float*)d_in[2];
    const float* b_ih0 = (const float*)d_in[3];
    const float* b_hh0 = (const float*)d_in[4];
    const float* w_ih1 = (const float*)d_in[5];
    const float* w_hh1 = (const float*)d_in[6];
    const float* b_ih1 = (const float*)d_in[7];
    const float* b_hh1 = (const float*)d_in[8];
    const float* h0    = (const float*)d_in[9];
    const float* c0    = (const float*)d_in[10];
    float* out = (float*)d_out;

    const int smem_bytes = 49600 * 4;  // 198400 B
    cudaFuncSetAttribute(lstm_rec, cudaFuncAttributeMaxDynamicSharedMemorySize,
                         smem_bytes);

    gemm_in2h<<<dim3(16, 256), 256>>>(x, w_ih0, b_ih0);
    lstm_rec<<<NBLK, 512, smem_bytes>>>(w_hh0, b_hh0, w_ih1, w_hh1, b_ih1, b_hh1,
                                        h0, c0, out);
}

// round 5
// speedup vs baseline: 1.3122x; 1.0618x over previous
#include <cuda_runtime.h>
#include <cstddef>

#define TT 1024
#define BB 32
#define NBLK 128
#define OUT1_ELEMS (TT*BB*512)
#define BH (BB*512)

#define WTS 20      // weight smem stride per k (16 rows + 4 pad)
#define HSS 516     // h smem row stride
#define PSS 132     // psm row stride: 32 batches * 4 kh + 4 pad

// ---------------- device globals (scratch; no allocation allowed) ------------
__device__ float g_gi0[(size_t)TT * BB * 2048];
__device__ float g_h0buf[2 * BH];
__device__ float g_h1buf[2 * BH];
__device__ unsigned g_flags[NBLK * 64];   // one 256B slot per block, monotonic gen

// ======================= input-projection GEMM ===============================
__global__ void __launch_bounds__(256) gemm_in2h(
    const float* __restrict__ A, const float* __restrict__ W,
    const float* __restrict__ bias)
{
    __shared__ float As[8][132];
    __shared__ float Bs[8][132];
    const int tid = threadIdx.x;
    const int n0 = blockIdx.x * 128;
    const int m0 = blockIdx.y * 128;
    const int tx = tid & 15, ty = tid >> 4;
    const int lrow = tid >> 1, lk4 = (tid & 1) * 4;
    const float* Ab = A + (size_t)(m0 + lrow) * 512 + lk4;
    const float* Wb = W + (size_t)(n0 + lrow) * 512 + lk4;

    float acc[8][8];
#pragma unroll
    for (int i = 0; i < 8; i++)
#pragma unroll
        for (int j = 0; j < 8; j++) acc[i][j] = 0.f;

    for (int k0 = 0; k0 < 512; k0 += 8) {
        float4 av = *(const float4*)(Ab + k0);
        float4 wv = *(const float4*)(Wb + k0);
        As[lk4 + 0][lrow] = av.x; As[lk4 + 1][lrow] = av.y;
        As[lk4 + 2][lrow] = av.z; As[lk4 + 3][lrow] = av.w;
        Bs[lk4 + 0][lrow] = wv.x; Bs[lk4 + 1][lrow] = wv.y;
        Bs[lk4 + 2][lrow] = wv.z; Bs[lk4 + 3][lrow] = wv.w;
        __syncthreads();
#pragma unroll
        for (int k = 0; k < 8; k++) {
            float a[8], b[8];
            *(float4*)&a[0] = *(const float4*)&As[k][ty * 8];
            *(float4*)&a[4] = *(const float4*)&As[k][ty * 8 + 4];
            *(float4*)&b[0] = *(const float4*)&Bs[k][tx * 8];
            *(float4*)&b[4] = *(const float4*)&Bs[k][tx * 8 + 4];
#pragma unroll
            for (int i = 0; i < 8; i++)
#pragma unroll
                for (int j = 0; j < 8; j++) acc[i][j] += a[i] * b[j];
        }
        __syncthreads();
    }

    float bv[8];
#pragma unroll
    for (int j = 0; j < 8; j++) bv[j] = bias[n0 + tx * 8 + j];
#pragma unroll
    for (int i = 0; i < 8; i++) {
        size_t row = (size_t)(m0 + ty * 8 + i);
        float* Crow = g_gi0 + row * 2048 + n0 + tx * 8;
#pragma unroll
        for (int j = 0; j < 8; j++) Crow[j] = acc[i][j] + bv[j];
    }
}

// ======================= persistent recurrence kernel ========================
__device__ __forceinline__ float sigf(float x) {
    float e = __expf(fminf(-x, 80.f));
    return __fdividef(1.f, 1.f + e);
}
__device__ __forceinline__ float tanhfast(float x) {
    float e = __expf(fminf(2.f * x, 80.f));
    return 1.f - __fdividef(2.f, e + 1.f);
}

__device__ __forceinline__ unsigned long long fma2(unsigned long long a,
                                                   unsigned long long b,
                                                   unsigned long long c) {
    unsigned long long d;
    asm("fma.rn.f32x2 %0, %1, %2, %3;" : "=l"(d) : "l"(a), "l"(b), "l"(c));
    return d;
}
__device__ __forceinline__ unsigned long long addf2(unsigned long long a,
                                                    unsigned long long b) {
    unsigned long long d;
    asm("add.rn.f32x2 %0, %1, %2;" : "=l"(d) : "l"(a), "l"(b));
    return d;
}

// distributed-flag barrier: per-block 256B slot, monotonic generation
__device__ __forceinline__ void flagbar(unsigned gen, int tid) {
    __syncthreads();
    if (tid == 0) {
        __threadfence();
        *(volatile unsigned*)&g_flags[blockIdx.x * 64] = gen;
    }
    if (tid < NBLK) {
        volatile unsigned* f = &g_flags[tid * 64];
        while (*f < gen) { }
    }
    __threadfence();
    __syncthreads();
}

// plain copy: src [32][512] contiguous -> hs rows of stride HSS
__device__ __forceinline__ void stage_h(float* __restrict__ hs,
                                        const float* __restrict__ src, int tid) {
#pragma unroll
    for (int it = 0; it < 8; it++) {
        int u4 = tid + it * 512;
        int b = u4 >> 7, k4 = (u4 & 127) << 2;
        *(float4*)(hs + b * HSS + k4) = ((const float4*)src)[u4];
    }
}

// warp covers: 2 batches (per thread) x 16 rows (8 f32x2 row-pairs) x 128 k
__device__ __forceinline__ void gemm_rp(const float* __restrict__ hs,
                                        const float* __restrict__ wt,
                                        int hbase, int kbase,
                                        unsigned long long acc[2][8]) {
    const float* hp = hs + hbase + kbase;
    const float* wp = wt + kbase * WTS;
#pragma unroll 4
    for (int m = 0; m < 16; m++) {
        float h0 = hp[m * 8];
        float h1 = hp[HSS + m * 8];
        unsigned long long H0, H1;
        asm("mov.b64 %0, {%1, %1};" : "=l"(H0) : "f"(h0));
        asm("mov.b64 %0, {%1, %1};" : "=l"(H1) : "f"(h1));
        const float* w = wp + m * 8 * WTS;
        ulonglong2 w01 = *(const ulonglong2*)(w);
        ulonglong2 w23 = *(const ulonglong2*)(w + 4);
        ulonglong2 w45 = *(const ulonglong2*)(w + 8);
        ulonglong2 w67 = *(const ulonglong2*)(w + 12);
        acc[0][0] = fma2(H0, w01.x, acc[0][0]); acc[1][0] = fma2(H1, w01.x, acc[1][0]);
        acc[0][1] = fma2(H0, w01.y, acc[0][1]); acc[1][1] = fma2(H1, w01.y, acc[1][1]);
        acc[0][2] = fma2(H0, w23.x, acc[0][2]); acc[1][2] = fma2(H1, w23.x, acc[1][2]);
        acc[0][3] = fma2(H0, w23.y, acc[0][3]); acc[1][3] = fma2(H1, w23.y, acc[1][3]);
        acc[0][4] = fma2(H0, w45.x, acc[0][4]); acc[1][4] = fma2(H1, w45.x, acc[1][4]);
        acc[0][5] = fma2(H0, w45.y, acc[0][5]); acc[1][5] = fma2(H1, w45.y, acc[1][5]);
        acc[0][6] = fma2(H0, w67.x, acc[0][6]); acc[1][6] = fma2(H1, w67.x, acc[1][6]);
        acc[0][7] = fma2(H0, w67.y, acc[0][7]); acc[1][7] = fma2(H1, w67.y, acc[1][7]);
    }
}

// reduce over the 8 kcl lanes; lane kcl writes row-pair j2 == kcl to psm[r][b][kh]
__device__ __forceinline__ void red_write_rp(unsigned long long acc[2][8],
                                             float* __restrict__ psm,
                                             int kh, int kcl, int b0t) {
#pragma unroll
    for (int j2 = 0; j2 < 8; j2++) {
#pragma unroll
        for (int b2 = 0; b2 < 2; b2++) {
            unsigned long long v = acc[b2][j2];
            v = addf2(v, __shfl_xor_sync(0xffffffffu, v, 1));
            v = addf2(v, __shfl_xor_sync(0xffffffffu, v, 2));
            v = addf2(v, __shfl_xor_sync(0xffffffffu, v, 4));
            acc[b2][j2] = v;
        }
        if (j2 == kcl) {
            float2 f0 = *(float2*)&acc[0][j2];
            float2 f1 = *(float2*)&acc[1][j2];
            psm[(2 * j2) * PSS     + b0t * 4       + kh] = f0.x;
            psm[(2 * j2 + 1) * PSS + b0t * 4       + kh] = f0.y;
            psm[(2 * j2) * PSS     + (b0t + 1) * 4 + kh] = f1.x;
            psm[(2 * j2 + 1) * PSS + (b0t + 1) * 4 + kh] = f1.y;
        }
    }
}

__global__ void __launch_bounds__(512, 1) lstm_rec(
    const float* __restrict__ w_hh0, const float* __restrict__ b_hh0,
    const float* __restrict__ w_ih1, const float* __restrict__ w_hh1,
    const float* __restrict__ b_ih1, const float* __restrict__ b_hh1,
    const float* __restrict__ h0_in, const float* __restrict__ c0_in,
    float* __restrict__ dout)
{
    extern __shared__ float sm[];
    float* ws0t  = sm;                    // 512*20 = 10240
    float* wsi1t = sm + 10240;
    float* wsh1t = sm + 20480;
    float* hs    = sm + 30720;            // 32*516 = 16512
    float* psmL0 = sm + 47232;            // 16*132 = 2112
    float* psmL1 = sm + 49344;            // 2112
    float* csm   = sm + 51456;            // 256

    const int tid = threadIdx.x;
    const int bid = blockIdx.x;
    const int J0 = bid << 2;

    // barrier generation base: all slots hold the same value at launch
    const unsigned gbase = *(volatile unsigned*)&g_flags[bid * 64];

    // Stage 16 weight rows per matrix, transposed to k-major [k][16].
    for (int u = tid; u < 16 * 512; u += 512) {
        int r = u >> 9, k = u & 511;
        int gr = ((r >> 2) << 9) + J0 + (r & 3);
        int d = k * WTS + r;
        ws0t[d]  = w_hh0[gr * 512 + k];
        wsi1t[d] = w_ih1[gr * 512 + k];
        wsh1t[d] = w_hh1[gr * 512 + k];
    }
    // init hidden buffers at parity 1 (read by interval 0 / interval 1)
    {
        int g = (bid << 9) + tid;
        if (g < BH)          g_h0buf[BH + g] = h0_in[g];
        else if (g < 2 * BH) g_h1buf[g]      = h0_in[g];
    }
    if (tid < 256) {
        int l = tid >> 7, jl = (tid >> 5) & 3, b = tid & 31;
        csm[tid] = c0_in[(l << 14) + (b << 9) + J0 + jl];
    }

    const int lane = tid & 31, warp = tid >> 5;
    const int bgrp = warp & 3, kh = warp >> 2;
    const int kcl = lane & 7, bsub = lane >> 3;
    const int b0t = bgrp * 8 + bsub * 2;
    const int kbase = kh * 128 + kcl;
    const int hbase = b0t * HSS;

    float bI0 = 0, bF0 = 0, bG0 = 0, bO0 = 0;
    float bI1 = 0, bF1 = 0, bG1 = 0, bO1 = 0;
    if (tid < 128) {
        int jl = tid >> 5, Jj = J0 + jl;
        bI0 = b_hh0[Jj];        bF0 = b_hh0[512 + Jj];
        bG0 = b_hh0[1024 + Jj]; bO0 = b_hh0[1536 + Jj];
    } else if (tid < 256) {
        int jl = (tid - 128) >> 5, Jj = J0 + jl;
        bI1 = b_ih1[Jj] + b_hh1[Jj];
        bF1 = b_ih1[512 + Jj] + b_hh1[512 + Jj];
        bG1 = b_ih1[1024 + Jj] + b_hh1[1024 + Jj];
        bO1 = b_ih1[1536 + Jj] + b_hh1[1536 + Jj];
    }

    flagbar(gbase + 1, tid);

    unsigned long long acc[2][8];

    // pipelined: interval v computes L0 step t0=v and L1 step t1=v-1
    for (int v = 0; v <= TT; v++) {
        const int p0 = v & 1, q0 = p0 ^ 1;

        // gi0 prefetch for L0 elementwise threads
        float giI = 0, giF = 0, giG = 0, giO = 0;
        if (v < TT && tid < 128) {
            int jl = tid >> 5, b = tid & 31, Jj = J0 + jl;
            const float* gi = g_gi0 + ((size_t)v << 16) + ((size_t)b << 11);
            giI = gi[Jj]; giF = gi[512 + Jj]; giG = gi[1024 + Jj]; giO = gi[1536 + Jj];
        }

        // ---- shared h0(v-1) staging (used by L0 w_hh0 and L1 w_ih1) ----
        stage_h(hs, g_h0buf + (q0 << 14), tid);
        __syncthreads();

        if (v < TT) {
#pragma unroll
            for (int b2 = 0; b2 < 2; b2++)
#pragma unroll
                for (int j2 = 0; j2 < 8; j2++) acc[b2][j2] = 0ull;
            gemm_rp(hs, ws0t, hbase, kbase, acc);
            red_write_rp(acc, psmL0, kh, kcl, b0t);
        }
        if (v > 0) {
#pragma unroll
            for (int b2 = 0; b2 < 2; b2++)
#pragma unroll
                for (int j2 = 0; j2 < 8; j2++) acc[b2][j2] = 0ull;
            gemm_rp(hs, wsi1t, hbase, kbase, acc);
        }
        __syncthreads();   // done reading hs

        if (v > 0) {
            stage_h(hs, g_h1buf + (p0 << 14), tid);  // h1(v-2), parity (v-2)&1 = p0
            __syncthreads();
            gemm_rp(hs, wsh1t, hbase, kbase, acc);   // accumulate
            red_write_rp(acc, psmL1, kh, kcl, b0t);
        }
        __syncthreads();   // psm ready

        // ---- L0 elementwise: step v ----
        if (v < TT && tid < 128) {
            int jl = tid >> 5, b = tid & 31, Jj = J0 + jl;
            float4 vI = *(const float4*)(psmL0 + (jl) * PSS + b * 4);
            float4 vF = *(const float4*)(psmL0 + (4 + jl) * PSS + b * 4);
            float4 vG = *(const float4*)(psmL0 + (8 + jl) * PSS + b * 4);
            float4 vO = *(const float4*)(psmL0 + (12 + jl) * PSS + b * 4);
            float gI = giI + bI0 + vI.x + vI.y + vI.z + vI.w;
            float gF = giF + bF0 + vF.x + vF.y + vF.z + vF.w;
            float gG = giG + bG0 + vG.x + vG.y + vG.z + vG.w;
            float gO = giO + bO0 + vO.x + vO.y + vO.z + vO.w;
            float iv = sigf(gI), fv = sigf(gF), gv = tanhfast(gG), ov = sigf(gO);
            float c = fv * csm[jl * 32 + b] + iv * gv;
            csm[jl * 32 + b] = c;
            float h = ov * tanhfast(c);
            g_h0buf[(p0 << 14) + (b << 9) + Jj] = h;
            if (v == TT - 1) {
                dout[OUT1_ELEMS + (b << 9) + Jj] = h;
                dout[OUT1_ELEMS + 2 * BH + (b << 9) + Jj] = c;
            }
        }

        // ---- L1 elementwise: step v-1 ----
        if (v > 0 && tid >= 128 && tid < 256) {
            int lt = tid - 128;
            int jl = lt >> 5, b = lt & 31, Jj = J0 + jl;
            float4 vI = *(const float4*)(psmL1 + (jl) * PSS + b * 4);
            float4 vF = *(const float4*)(psmL1 + (4 + jl) * PSS + b * 4);
            float4 vG = *(const float4*)(psmL1 + (8 + jl) * PSS + b * 4);
            float4 vO = *(const float4*)(psmL1 + (12 + jl) * PSS + b * 4);
            float gI = bI1 + vI.x + vI.y + vI.z + vI.w;
            float gF = bF1 + vF.x + vF.y + vF.z + vF.w;
            float gG = bG1 + vG.x + vG.y + vG.z + vG.w;
            float gO = bO1 + vO.x + vO.y + vO.z + vO.w;
            float iv = sigf(gI), fv = sigf(gF), gv = tanhfast(gG), ov = sigf(gO);
            float c = fv * csm[128 + jl * 32 + b] + iv * gv;
            csm[128 + jl * 32 + b] = c;
            float h = ov * tanhfast(c);
            g_h1buf[(q0 << 14) + (b << 9) + Jj] = h;   // parity (v-1)&1 = q0
            int t1 = v - 1;
            dout[((size_t)t1 << 14) + (b << 9) + Jj] = h;
            if (v == TT) {
                dout[OUT1_ELEMS + BH + (b << 9) + Jj] = h;
                dout[OUT1_ELEMS + 2 * BH + BH + (b << 9) + Jj] = c;
            }
        }

        flagbar(gbase + v + 2, tid);
    }
}

// ============================== launcher =====================================
extern "C" void kernel_launch(void* const* d_in, const int* in_sizes, int n_in,
                              void* d_out, int out_size) {
    const float* x     = (const float*)d_in[0];
    const float* w_ih0 = (const float*)d_in[1];
    const float* w_hh0 = (const float*)d_in[2];
    const float* b_ih0 = (const float*)d_in[3];
    const float* b_hh0 = (const float*)d_in[4];
    const float* w_ih1 = (const float*)d_in[5];
    const float* w_hh1 = (const float*)d_in[6];
    const float* b_ih1 = (const float*)d_in[7];
    const float* b_hh1 = (const float*)d_in[8];
    const float* h0    = (const float*)d_in[9];
    const float* c0    = (const float*)d_in[10];
    float* out = (float*)d_out;

    const int smem_bytes = 51712 * 4;  // 206848 B
    cudaFuncSetAttribute(lstm_rec, cudaFuncAttributeMaxDynamicSharedMemorySize,
                         smem_bytes);

    gemm_in2h<<<dim3(16, 256), 256>>>(x, w_ih0, b_ih0);
    lstm_rec<<<NBLK, 512, smem_bytes>>>(w_hh0, b_hh0, w_ih1, w_hh1, b_ih1, b_hh1,
                                        h0, c0, out);
}